// round 11
// baseline (speedup 1.0000x reference)
#include <cuda_runtime.h>
#include <cuda_fp16.h>
#include <math.h>

namespace {

constexpr int Bsz = 4, T = 2048, D = 512, E = 4, C = 1024, HE = 512, O = 512;
constexpr int SMEM_DYN = 98304 + 1024;
constexpr int GMAX = 296;   // 148 SMs x 2 CTAs

// hi-only operands: blob per (128-row mtile, 32-k chunk):
//   [row 0..127][32 halfs; 16B-unit u in 0..3 at u^((row>>1)&3)]  (4096 halfs)
// full hi/lo operands (GEMM-epilogue-produced):
//   [row 0..127][64 halfs = 32hi|32lo; 16B-unit u in 0..7 at u^(row&7)] (8192 halfs)
__device__ __align__(256) unsigned short g_A1p[(size_t)Bsz*E*C*T];      // dm^T hi  [be]
__device__ __align__(256) unsigned short g_B1p[(size_t)Bsz*D*T];        // x^T  hi  [b]
__device__ __align__(256) unsigned short g_B2p[(size_t)E*HE*D];         // w1^T hi  [e]
__device__ __align__(256) unsigned short g_B3p[(size_t)E*O*HE];         // w2^T hi  [e]
__device__ __align__(256) unsigned short g_A2p[(size_t)Bsz*E*C*2*D];    // xd  full [be]
__device__ __align__(256) unsigned short g_A3p[(size_t)Bsz*E*C*2*HE];   // h   full [be]
__device__ __align__(256) float          g_y  [(size_t)Bsz*E*C*O];      // fp32 y
__device__ __align__(256) unsigned short g_B4p[(size_t)Bsz*O*E*C];      // y^T  hi  [b]
__device__ __align__(256) unsigned short g_A4p[(size_t)Bsz*T*E*C];      // comb hi  [b]

__device__ __forceinline__ unsigned smem_u32(const void* p) {
    unsigned a;
    asm("{ .reg .u64 t; cvta.to.shared.u64 t, %1; cvt.u32.u64 %0, t; }" : "=r"(a) : "l"(p));
    return a;
}
__device__ __forceinline__ void split_h(float v, __half& h, __half& l) {
    h = __float2half_rn(v);
    l = __float2half_rn(v - __half2float(h));
}
__device__ __forceinline__ float gelu(float v) {
    return 0.5f * v * (1.0f + erff(v * 0.70710678118654752f));
}
__device__ __forceinline__ unsigned pack2h(float a, float b) {
    __half2 p; p.x = __float2half_rn(a); p.y = __float2half_rn(b);
    return *(unsigned*)&p;
}

__device__ __forceinline__ void mbar_init(unsigned a, unsigned cnt) {
    asm volatile("mbarrier.init.shared.b64 [%0], %1;" :: "r"(a), "r"(cnt) : "memory");
}
__device__ __forceinline__ void mbar_arrive(unsigned a) {
    asm volatile("mbarrier.arrive.shared.b64 _, [%0];" :: "r"(a) : "memory");
}
__device__ __forceinline__ void mbar_expect_tx(unsigned a, unsigned bytes) {
    asm volatile("mbarrier.arrive.expect_tx.shared.b64 _, [%0], %1;"
                 :: "r"(a), "r"(bytes) : "memory");
}
__device__ __forceinline__ void mbar_wait(unsigned a, unsigned par) {
    asm volatile("{\n\t.reg .pred P;\n"
                 "WL%=:\n\t"
                 "mbarrier.try_wait.parity.acquire.cta.shared::cta.b64 P, [%0], %1, 0x989680;\n\t"
                 "@P bra.uni WD%=;\n\t"
                 "bra.uni WL%=;\n"
                 "WD%=:\n\t}" :: "r"(a), "r"(par) : "memory");
}
__device__ __forceinline__ void bulk_g2s(unsigned dst, const void* src,
                                         unsigned bytes, unsigned mbar) {
    asm volatile("cp.async.bulk.shared::cluster.global.mbarrier::complete_tx::bytes "
                 "[%0], [%1], %2, [%3];"
                 :: "r"(dst), "l"(src), "r"(bytes), "r"(mbar) : "memory");
}

#define LDSM_X4(R, addr) \
    asm volatile("ldmatrix.sync.aligned.m8n8.x4.shared.b16 {%0,%1,%2,%3}, [%4];" \
        : "=r"((R)[0]), "=r"((R)[1]), "=r"((R)[2]), "=r"((R)[3]) : "r"(addr))

#define MMA_F16(Cc, Aa, Bb) \
    asm volatile("mma.sync.aligned.m16n8k16.row.col.f32.f16.f16.f32 " \
        "{%0,%1,%2,%3}, {%4,%5,%6,%7}, {%8,%9}, {%0,%1,%2,%3};" \
        : "+f"((Cc)[0]), "+f"((Cc)[1]), "+f"((Cc)[2]), "+f"((Cc)[3]) \
        : "r"((Aa)[0]), "r"((Aa)[1]), "r"((Aa)[2]), "r"((Aa)[3]), \
          "r"((Bb)[0]), "r"((Bb)[1]))

// ---------------- coalesced hi-only pack kernels ----------------
__global__ void pack_hi_t(const float* __restrict__ inBase, unsigned short* __restrict__ outRaw,
                          int Kdim, int rs, long inZdiv, long inZmod, int zdiv, long outZ) {
    int z = blockIdx.z;
    const float* in = inBase + (long)(z / zdiv) * inZdiv + (long)(z % zdiv) * inZmod;
    __half* out = (__half*)outRaw + (long)z * outZ;
    __shared__ float t[32][132];
    const int m0 = blockIdx.x * 128, k0 = blockIdx.y * 32;
    const int tid = threadIdx.x;
    const int lr = tid >> 5, lc = (tid & 31) * 4;
    #pragma unroll
    for (int i = 0; i < 4; ++i) {
        float4 v = *(const float4*)&in[(long)(k0 + lr + 8*i) * rs + m0 + lc];
        t[lr + 8*i][lc] = v.x; t[lr + 8*i][lc+1] = v.y;
        t[lr + 8*i][lc+2] = v.z; t[lr + 8*i][lc+3] = v.w;
    }
    __syncthreads();
    const int m = tid >> 1, hf = tid & 1;
    const int mg = m0 + m;
    long blob = ((long)(mg >> 7) * (Kdim >> 5) + blockIdx.y) * 4096 + (mg & 127) * 32;
    const unsigned sw = (unsigned)((mg >> 1) & 3);
    unsigned w[4], w2[4];
    #pragma unroll
    for (int q = 0; q < 4; ++q)
        w[q] = pack2h(t[hf*16 + q*2][m], t[hf*16 + q*2 + 1][m]);
    #pragma unroll
    for (int q = 0; q < 4; ++q)
        w2[q] = pack2h(t[hf*16 + 8 + q*2][m], t[hf*16 + 8 + q*2 + 1][m]);
    const unsigned u0 = (unsigned)(hf * 2), u1 = u0 + 1;
    *(uint4*)(out + blob + ((u0 ^ sw) << 3)) = make_uint4(w[0], w[1], w[2], w[3]);
    *(uint4*)(out + blob + ((u1 ^ sw) << 3)) = make_uint4(w2[0], w2[1], w2[2], w2[3]);
}

__global__ void pack_hi_nt(const float* __restrict__ in, unsigned short* __restrict__ outRaw,
                           long nUnits, int Kdim) {
    long i = (long)blockIdx.x * blockDim.x + threadIdx.x;
    if (i >= nUnits) return;
    const int upr = Kdim >> 3;
    long r = i / upr; int uq = (int)(i % upr);
    int g = uq >> 2, u = uq & 3;
    const float* src = in + r * Kdim + g * 32 + u * 8;
    float4 a = *(const float4*)src, b = *(const float4*)(src + 4);
    __half* out = (__half*)outRaw;
    long blob = ((r >> 7) * (long)(Kdim >> 5) + g) * 4096 + (r & 127) * 32;
    unsigned sw = (unsigned)((r >> 1) & 3);
    *(uint4*)(out + blob + ((((unsigned)u) ^ sw) << 3)) =
        make_uint4(pack2h(a.x, a.y), pack2h(a.z, a.w), pack2h(b.x, b.y), pack2h(b.z, b.w));
}

// ------- persistent mma.sync fp16 GEMM, 4 warps x 64x64, TMA-bulk, continuous producer -------
// ALO=1: C = (A_hi + A_lo) * B_hi ; ALO=0: C = A_hi * B_hi
// EPI: 0 = packed full hi/lo out; 1 = + bias + GELU; 2 = fp32 out; 3 = fp32 out + bias
template <int EPI, int ALO, int KG, int NSTG>
__global__ __launch_bounds__(128, 2)
void bgemm(const unsigned short* __restrict__ Ap,
           const unsigned short* __restrict__ Bp,
           void* __restrict__ Cout,
           const float* __restrict__ biasBase,
           int K, int Nn, int ldc,
           long Az, long Bz, long Cz, long biasZ,
           int bDiv, int tX, int tXY, int nTiles)
{
    constexpr int ATB = ALO ? 16384 : 8192;
    constexpr int BTB = 8192;
    constexpr int STB = KG * (ATB + BTB);
    extern __shared__ char dynsm[];
    __shared__ __align__(8) unsigned long long s_full[NSTG], s_empty[NSTG];

    const int bid = blockIdx.x, G = gridDim.x;
    if (bid >= nTiles) return;
    const unsigned smBase = (smem_u32(dynsm) + 1023u) & ~1023u;

    const int tid  = threadIdx.x;
    const int lane = tid & 31;
    const int warp = tid >> 5;
    const int wm   = warp & 1;   // 0..1 -> 64-row block
    const int wn   = warp >> 1;  // 0..1 -> 64-col block
    const int gid  = lane >> 2, tig = lane & 3;

    const int nch = K / 32, spt = nch / KG;
    const int myTiles  = (nTiles - bid + G - 1) / G;
    const int myStages = myTiles * spt;

    unsigned fullB[NSTG], emptyB[NSTG];
    #pragma unroll
    for (int s = 0; s < NSTG; ++s) {
        fullB[s]  = smem_u32(&s_full[s]);
        emptyB[s] = smem_u32(&s_empty[s]);
    }
    if (tid == 0) {
        #pragma unroll
        for (int s = 0; s < NSTG; ++s) { mbar_init(fullB[s], 1); mbar_init(emptyB[s], 4); }
    }
    __syncthreads();

    // ---- producer state (continuous across tiles) ----
    int ptile = bid, pStage = 0, pslot = 0, pph = 0, pcount = 0;
    const char *pgA, *pgB;
    {
        int z = ptile / tXY, r0 = ptile - z * tXY, ty = r0 / tX, tx = r0 - ty * tX;
        pgA = (const char*)(Ap + (long)z * Az) + (long)ty * nch * ATB;
        pgB = (const char*)(Bp + (long)((z / bDiv) % E) * Bz) + (long)tx * nch * BTB;
    }

    auto produce = [&]() {
        if (tid == 0) {
            if (pcount >= NSTG) mbar_wait(emptyB[pslot], pph ^ 1);
            mbar_expect_tx(fullB[pslot], STB);
            bulk_g2s(smBase + pslot * STB,          pgA + (long)pStage * (KG * ATB), KG * ATB, fullB[pslot]);
            bulk_g2s(smBase + pslot * STB + KG*ATB, pgB + (long)pStage * (KG * BTB), KG * BTB, fullB[pslot]);
        }
        ++pcount;
        if (++pslot == NSTG) { pslot = 0; pph ^= 1; }
        if (++pStage == spt) {
            pStage = 0; ptile += G;
            if (ptile < nTiles) {
                int z = ptile / tXY, r0 = ptile - z * tXY, ty = r0 / tX, tx = r0 - ty * tX;
                pgA = (const char*)(Ap + (long)z * Az) + (long)ty * nch * ATB;
                pgB = (const char*)(Bp + (long)((z / bDiv) % E) * Bz) + (long)tx * nch * BTB;
            }
        }
    };

    for (int i = 0; i < NSTG - 1 && i < myStages; ++i) produce();

    float acc[4][8][4];
    #pragma unroll
    for (int a = 0; a < 4; ++a)
        #pragma unroll
        for (int b = 0; b < 8; ++b)
            #pragma unroll
            for (int q = 0; q < 4; ++q) acc[a][b][q] = 0.0f;

    int cs = 0, cp = 0, cKg = 0, ctile = bid;

    for (int s = 0; s < myStages; ++s) {
        if (s + NSTG - 1 < myStages) produce();
        mbar_wait(fullB[cs], cp);

        const unsigned stg = smBase + cs * STB;
        #pragma unroll
        for (int kg = 0; kg < KG; ++kg) {
            const unsigned aB = stg + kg * ATB;
            const unsigned bB = stg + KG * ATB + kg * BTB;
            #pragma unroll
            for (int ks = 0; ks < 2; ++ks) {
                unsigned aH[4][4], aL[4][4];
                #pragma unroll
                for (int mt = 0; mt < 4; ++mt) {
                    unsigned r = wm * 64 + mt * 16 + (lane & 15);
                    if (ALO) {
                        unsigned ca = (unsigned)(lane >> 4);
                        LDSM_X4(aH[mt], aB + r * 128 + ((((unsigned)(ks*2) + ca) ^ (r & 7)) << 4));
                        LDSM_X4(aL[mt], aB + r * 128 + ((((unsigned)(4 + ks*2) + ca) ^ (r & 7)) << 4));
                    } else {
                        unsigned cu = (unsigned)(ks * 2 + (lane >> 4));
                        LDSM_X4(aH[mt], aB + r * 64 + ((cu ^ ((r >> 1) & 3)) << 4));
                    }
                }
                #pragma unroll
                for (int p = 0; p < 4; ++p) {
                    unsigned bH[4];
                    unsigned r = wn * 64 + p * 16 + (lane & 7) + ((lane >> 4) << 3);
                    unsigned cu = (unsigned)(ks * 2 + ((lane >> 3) & 1));
                    LDSM_X4(bH, bB + r * 64 + ((cu ^ ((r >> 1) & 3)) << 4));
                    #pragma unroll
                    for (int mt = 0; mt < 4; ++mt)
                        #pragma unroll
                        for (int s2 = 0; s2 < 2; ++s2) {
                            float* cc = acc[mt][p * 2 + s2];
                            MMA_F16(cc, aH[mt], bH + 2 * s2);
                            if (ALO) MMA_F16(cc, aL[mt], bH + 2 * s2);
                        }
                }
            }
        }
        if (lane == 0) mbar_arrive(emptyB[cs]);
        if (++cs == NSTG) { cs = 0; cp ^= 1; }

        if (++cKg == spt) {
            // ---- epilogue for ctile (producer already prefetching next tile) ----
            int z = ctile / tXY, r0 = ctile - z * tXY, ty = r0 / tX, tx = r0 - ty * tX;
            const int crow = ty * 128, ccol = tx * 128;
            const int bIdx = (z / bDiv) % E;
            const float* bias = (EPI == 1 || EPI == 3) ? (biasBase + (long)bIdx * biasZ) : nullptr;

            #pragma unroll
            for (int mt = 0; mt < 4; ++mt) {
                #pragma unroll
                for (int half = 0; half < 2; ++half) {
                    const int r = crow + wm * 64 + mt * 16 + gid + 8 * half;
                    if (EPI <= 1) {
                        unsigned short* dstz = (unsigned short*)Cout + (long)z * Cz;
                        long rowBase = (long)(r >> 7) * (Nn >> 5) * 8192 + (long)(r & 127) * 64;
                        const int ru = r & 7;
                        #pragma unroll
                        for (int nj = 0; nj < 8; ++nj) {
                            const int cg = ccol + wn * 64 + nj * 8 + 2 * tig;
                            float v0 = acc[mt][nj][2 * half];
                            float v1 = acc[mt][nj][2 * half + 1];
                            if (EPI == 1) {
                                v0 = gelu(v0 + bias[cg]);
                                v1 = gelu(v1 + bias[cg + 1]);
                            }
                            __half h0, l0, h1, l1;
                            split_h(v0, h0, l0); split_h(v1, h1, l1);
                            __half2 ph; ph.x = h0; ph.y = h1;
                            __half2 pl; pl.x = l0; pl.y = l1;
                            const int g = cg >> 5, j = cg & 31;
                            long tb = rowBase + (long)g * 8192;
                            int u0 = j >> 3;
                            int jp0 = (((u0 ^ ru) & 7) << 3) | (j & 7);
                            int u1 = 4 + u0;
                            int jp1 = (((u1 ^ ru) & 7) << 3) | (j & 7);
                            *(__half2*)(dstz + tb + jp0) = ph;
                            *(__half2*)(dstz + tb + jp1) = pl;
                        }
                    } else {
                        float* dst = (float*)Cout + (long)z * Cz + (long)r * ldc;
                        #pragma unroll
                        for (int nj = 0; nj < 8; ++nj) {
                            const int cg = ccol + wn * 64 + nj * 8 + 2 * tig;
                            float v0 = acc[mt][nj][2 * half];
                            float v1 = acc[mt][nj][2 * half + 1];
                            if (EPI == 3) { v0 += bias[cg]; v1 += bias[cg + 1]; }
                            float2 p; p.x = v0; p.y = v1;
                            *(float2*)(dst + cg) = p;
                        }
                    }
                }
            }
            cKg = 0; ctile += G;
            #pragma unroll
            for (int a = 0; a < 4; ++a)
                #pragma unroll
                for (int b = 0; b < 8; ++b)
                    #pragma unroll
                    for (int q = 0; q < 4; ++q) acc[a][b][q] = 0.0f;
        }
    }
}

} // namespace

extern "C" void kernel_launch(void* const* d_in, const int* in_sizes, int n_in,
                              void* d_out, int out_size)
{
    const float* x    = (const float*)d_in[0];
    const float* dm   = (const float*)d_in[1];
    const float* comb = (const float*)d_in[2];
    const float* w1   = (const float*)d_in[3];
    const float* b1   = (const float*)d_in[4];
    const float* w2   = (const float*)d_in[5];
    const float* b2   = (const float*)d_in[6];
    float* out = (float*)d_out;

    unsigned short *A1p, *B1p, *B2p, *B3p, *A2p, *A3p, *B4p, *A4p;
    float* yscr;
    cudaGetSymbolAddress((void**)&A1p, g_A1p);
    cudaGetSymbolAddress((void**)&B1p, g_B1p);
    cudaGetSymbolAddress((void**)&B2p, g_B2p);
    cudaGetSymbolAddress((void**)&B3p, g_B3p);
    cudaGetSymbolAddress((void**)&A2p, g_A2p);
    cudaGetSymbolAddress((void**)&A3p, g_A3p);
    cudaGetSymbolAddress((void**)&B4p, g_B4p);
    cudaGetSymbolAddress((void**)&A4p, g_A4p);
    cudaGetSymbolAddress((void**)&yscr, g_y);

    cudaFuncSetAttribute(bgemm<0,0,2,3>, cudaFuncAttributeMaxDynamicSharedMemorySize, SMEM_DYN);
    cudaFuncSetAttribute(bgemm<1,1,1,4>, cudaFuncAttributeMaxDynamicSharedMemorySize, SMEM_DYN);
    cudaFuncSetAttribute(bgemm<2,1,1,4>, cudaFuncAttributeMaxDynamicSharedMemorySize, SMEM_DYN);
    cudaFuncSetAttribute(bgemm<3,0,2,3>, cudaFuncAttributeMaxDynamicSharedMemorySize, SMEM_DYN);

    // #1 dm^T -> A1p (hi): per (b,e)
    pack_hi_t<<<dim3(C/128, T/32, Bsz*E), 256>>>(dm, A1p, T, E*C,
        (long)T*E*C, (long)C, E, (long)C*T);
    // #2 x^T -> B1p (hi): per b
    pack_hi_t<<<dim3(D/128, T/32, Bsz), 256>>>(x, B1p, T, D,
        (long)T*D, 0L, 1, (long)D*T);
    // #3 w1^T -> B2p (hi): per e
    pack_hi_t<<<dim3(HE/128, D/32, E), 256>>>(w1, B2p, D, HE,
        (long)D*HE, 0L, 1, (long)HE*D);
    // #4 S1: xd = dm^T * x  (M=C, N=D, K=T) -> A2p (full)   [profiled slot]
    {
        int nT = (D/128) * (C/128) * (Bsz*E);   // 512
        bgemm<0,0,2,3><<<(nT < GMAX ? nT : GMAX), 128, SMEM_DYN>>>(
            A1p, B1p, A2p, nullptr, T, D, D,
            (long)C*T, (long)D*T, (long)C*2*D, 0L,
            4, D/128, (D/128)*(C/128), nT);
    }
    // #5 w2^T -> B3p (hi): per e
    pack_hi_t<<<dim3(O/128, HE/32, E), 256>>>(w2, B3p, HE, O,
        (long)HE*O, 0L, 1, (long)O*HE);
    // #6 comb -> A4p (hi)
    {
        long nUnits = (long)Bsz * T * E * C / 8;
        pack_hi_nt<<<(unsigned)((nUnits + 255) / 256), 256>>>(comb, A4p, nUnits, E*C);
    }
    // #7 S2: h = gelu(xd*w1 + b1)  (K=D) -> A3p (full)
    {
        int nT = (HE/128) * (C/128) * (Bsz*E);  // 512
        bgemm<1,1,1,4><<<(nT < GMAX ? nT : GMAX), 128, SMEM_DYN>>>(
            A2p, B2p, A3p, b1, D, HE, HE,
            (long)C*2*D, (long)HE*D, (long)C*2*HE, (long)HE,
            1, HE/128, (HE/128)*(C/128), nT);
    }
    // #8 S3: y = h*w2  (K=HE) fp32 -> yscr
    {
        int nT = (O/128) * (C/128) * (Bsz*E);   // 512
        bgemm<2,1,1,4><<<(nT < GMAX ? nT : GMAX), 128, SMEM_DYN>>>(
            A3p, B3p, yscr, nullptr, HE, O, O,
            (long)C*2*HE, (long)O*HE, (long)C*O, 0L,
            1, O/128, (O/128)*(C/128), nT);
    }
    // #9 y^T -> B4p (hi): per b
    pack_hi_t<<<dim3(O/128, (E*C)/32, Bsz), 256>>>(yscr, B4p, E*C, O,
        (long)E*C*O, 0L, 1, (long)O*E*C);
    // #10 S4: out = comb * y^T + b2  (M=T, N=O, K=EC) fp32 out
    {
        int nT = (O/128) * (T/128) * Bsz;       // 256
        bgemm<3,0,2,3><<<(nT < GMAX ? nT : GMAX), 128, SMEM_DYN>>>(
            A4p, B4p, out, b2, E*C, O, O,
            (long)T*E*C, (long)O*E*C, (long)T*O, 0L,
            1, O/128, (O/128)*(T/128), nT);
    }
}

// round 12
// speedup vs baseline: 1.1390x; 1.1390x over previous
#include <cuda_runtime.h>
#include <cuda_fp16.h>
#include <math.h>

namespace {

constexpr int Bsz = 4, T = 2048, D = 512, E = 4, C = 1024, HE = 512, O = 512;
constexpr int SMEM_DYN = 98304 + 1024;
constexpr int GMAX = 296;   // 148 SMs x 2 CTAs

// ALL operands hi-only fp16, blob per (128-row tile, 32-k chunk):
//   [row 0..127][32 halfs; 16B-unit u in 0..3 at u^((row>>1)&3)]  (4096 halfs = 8KB)
__device__ __align__(256) unsigned short g_A1p[(size_t)Bsz*E*C*T];      // dm^T [be]
__device__ __align__(256) unsigned short g_B1p[(size_t)Bsz*D*T];        // x^T  [b]
__device__ __align__(256) unsigned short g_B2p[(size_t)E*HE*D];         // w1^T [e]
__device__ __align__(256) unsigned short g_B3p[(size_t)E*O*HE];         // w2^T [e]
__device__ __align__(256) unsigned short g_A2p[(size_t)Bsz*E*C*D];      // xd   [be]
__device__ __align__(256) unsigned short g_A3p[(size_t)Bsz*E*C*HE];     // h    [be]
__device__ __align__(256) float          g_y  [(size_t)Bsz*E*C*O];      // fp32 y
__device__ __align__(256) unsigned short g_B4p[(size_t)Bsz*O*E*C];      // y^T  [b]
__device__ __align__(256) unsigned short g_A4p[(size_t)Bsz*T*E*C];      // comb [b]

__device__ __forceinline__ unsigned smem_u32(const void* p) {
    unsigned a;
    asm("{ .reg .u64 t; cvta.to.shared.u64 t, %1; cvt.u32.u64 %0, t; }" : "=r"(a) : "l"(p));
    return a;
}
__device__ __forceinline__ float gelu(float v) {
    return 0.5f * v * (1.0f + erff(v * 0.70710678118654752f));
}
__device__ __forceinline__ unsigned pack2h(float a, float b) {
    __half2 p; p.x = __float2half_rn(a); p.y = __float2half_rn(b);
    return *(unsigned*)&p;
}

__device__ __forceinline__ void mbar_init(unsigned a, unsigned cnt) {
    asm volatile("mbarrier.init.shared.b64 [%0], %1;" :: "r"(a), "r"(cnt) : "memory");
}
__device__ __forceinline__ void mbar_arrive(unsigned a) {
    asm volatile("mbarrier.arrive.shared.b64 _, [%0];" :: "r"(a) : "memory");
}
__device__ __forceinline__ void mbar_expect_tx(unsigned a, unsigned bytes) {
    asm volatile("mbarrier.arrive.expect_tx.shared.b64 _, [%0], %1;"
                 :: "r"(a), "r"(bytes) : "memory");
}
__device__ __forceinline__ void mbar_wait(unsigned a, unsigned par) {
    asm volatile("{\n\t.reg .pred P;\n"
                 "WL%=:\n\t"
                 "mbarrier.try_wait.parity.acquire.cta.shared::cta.b64 P, [%0], %1, 0x989680;\n\t"
                 "@P bra.uni WD%=;\n\t"
                 "bra.uni WL%=;\n"
                 "WD%=:\n\t}" :: "r"(a), "r"(par) : "memory");
}
__device__ __forceinline__ void bulk_g2s(unsigned dst, const void* src,
                                         unsigned bytes, unsigned mbar) {
    asm volatile("cp.async.bulk.shared::cluster.global.mbarrier::complete_tx::bytes "
                 "[%0], [%1], %2, [%3];"
                 :: "r"(dst), "l"(src), "r"(bytes), "r"(mbar) : "memory");
}

#define LDSM_X4(R, addr) \
    asm volatile("ldmatrix.sync.aligned.m8n8.x4.shared.b16 {%0,%1,%2,%3}, [%4];" \
        : "=r"((R)[0]), "=r"((R)[1]), "=r"((R)[2]), "=r"((R)[3]) : "r"(addr))

#define MMA_F16(Cc, Aa, Bb) \
    asm volatile("mma.sync.aligned.m16n8k16.row.col.f32.f16.f16.f32 " \
        "{%0,%1,%2,%3}, {%4,%5,%6,%7}, {%8,%9}, {%0,%1,%2,%3};" \
        : "+f"((Cc)[0]), "+f"((Cc)[1]), "+f"((Cc)[2]), "+f"((Cc)[3]) \
        : "r"((Aa)[0]), "r"((Aa)[1]), "r"((Aa)[2]), "r"((Aa)[3]), \
          "r"((Bb)[0]), "r"((Bb)[1]))

// ---------------- coalesced hi-only pack kernels ----------------
__global__ void pack_hi_t(const float* __restrict__ inBase, unsigned short* __restrict__ outRaw,
                          int Kdim, int rs, long inZdiv, long inZmod, int zdiv, long outZ) {
    int z = blockIdx.z;
    const float* in = inBase + (long)(z / zdiv) * inZdiv + (long)(z % zdiv) * inZmod;
    __half* out = (__half*)outRaw + (long)z * outZ;
    __shared__ float t[32][132];
    const int m0 = blockIdx.x * 128, k0 = blockIdx.y * 32;
    const int tid = threadIdx.x;
    const int lr = tid >> 5, lc = (tid & 31) * 4;
    #pragma unroll
    for (int i = 0; i < 4; ++i) {
        float4 v = *(const float4*)&in[(long)(k0 + lr + 8*i) * rs + m0 + lc];
        t[lr + 8*i][lc] = v.x; t[lr + 8*i][lc+1] = v.y;
        t[lr + 8*i][lc+2] = v.z; t[lr + 8*i][lc+3] = v.w;
    }
    __syncthreads();
    const int m = tid >> 1, hf = tid & 1;
    const int mg = m0 + m;
    long blob = ((long)(mg >> 7) * (Kdim >> 5) + blockIdx.y) * 4096 + (mg & 127) * 32;
    const unsigned sw = (unsigned)((mg >> 1) & 3);
    unsigned w[4], w2[4];
    #pragma unroll
    for (int q = 0; q < 4; ++q)
        w[q] = pack2h(t[hf*16 + q*2][m], t[hf*16 + q*2 + 1][m]);
    #pragma unroll
    for (int q = 0; q < 4; ++q)
        w2[q] = pack2h(t[hf*16 + 8 + q*2][m], t[hf*16 + 8 + q*2 + 1][m]);
    const unsigned u0 = (unsigned)(hf * 2), u1 = u0 + 1;
    *(uint4*)(out + blob + ((u0 ^ sw) << 3)) = make_uint4(w[0], w[1], w[2], w[3]);
    *(uint4*)(out + blob + ((u1 ^ sw) << 3)) = make_uint4(w2[0], w2[1], w2[2], w2[3]);
}

__global__ void pack_hi_nt(const float* __restrict__ in, unsigned short* __restrict__ outRaw,
                           long nUnits, int Kdim) {
    long i = (long)blockIdx.x * blockDim.x + threadIdx.x;
    if (i >= nUnits) return;
    const int upr = Kdim >> 3;
    long r = i / upr; int uq = (int)(i % upr);
    int g = uq >> 2, u = uq & 3;
    const float* src = in + r * Kdim + g * 32 + u * 8;
    float4 a = *(const float4*)src, b = *(const float4*)(src + 4);
    __half* out = (__half*)outRaw;
    long blob = ((r >> 7) * (long)(Kdim >> 5) + g) * 4096 + (r & 127) * 32;
    unsigned sw = (unsigned)((r >> 1) & 3);
    *(uint4*)(out + blob + ((((unsigned)u) ^ sw) << 3)) =
        make_uint4(pack2h(a.x, a.y), pack2h(a.z, a.w), pack2h(b.x, b.y), pack2h(b.z, b.w));
}

// ------- persistent mma.sync fp16 GEMM (all-hi), TMA-bulk, continuous producer -------
// C = A_hi * B_hi
// EPI: 0 = packed hi out; 1 = packed hi out + bias + GELU; 2 = fp32 out; 3 = fp32 out + bias
template <int EPI, int KG, int NSTG>
__global__ __launch_bounds__(256, 2)
void bgemm(const unsigned short* __restrict__ Ap,
           const unsigned short* __restrict__ Bp,
           void* __restrict__ Cout,
           const float* __restrict__ biasBase,
           int K, int Nn, int ldc,
           long Az, long Bz, long Cz, long biasZ,
           int bDiv, int tX, int tXY, int nTiles)
{
    constexpr int TB = 8192;
    constexpr int STB = KG * 2 * TB;
    extern __shared__ char dynsm[];
    __shared__ __align__(8) unsigned long long s_full[NSTG], s_empty[NSTG];

    const int bid = blockIdx.x, G = gridDim.x;
    if (bid >= nTiles) return;
    const unsigned smBase = (smem_u32(dynsm) + 1023u) & ~1023u;

    const int tid  = threadIdx.x;
    const int lane = tid & 31;
    const int warp = tid >> 5;
    const int wm   = warp & 3;
    const int wn   = warp >> 2;
    const int gid  = lane >> 2, tig = lane & 3;

    const int nch = K / 32, spt = nch / KG;
    const int myTiles  = (nTiles - bid + G - 1) / G;
    const int myStages = myTiles * spt;

    unsigned fullB[NSTG], emptyB[NSTG];
    #pragma unroll
    for (int s = 0; s < NSTG; ++s) {
        fullB[s]  = smem_u32(&s_full[s]);
        emptyB[s] = smem_u32(&s_empty[s]);
    }
    if (tid == 0) {
        #pragma unroll
        for (int s = 0; s < NSTG; ++s) { mbar_init(fullB[s], 1); mbar_init(emptyB[s], 8); }
    }
    __syncthreads();

    // ---- producer state (continuous across tiles) ----
    int ptile = bid, pStage = 0, pslot = 0, pph = 0, pcount = 0;
    const char *pgA, *pgB;
    {
        int z = ptile / tXY, r0 = ptile - z * tXY, ty = r0 / tX, tx = r0 - ty * tX;
        pgA = (const char*)(Ap + (long)z * Az) + (long)ty * nch * TB;
        pgB = (const char*)(Bp + (long)((z / bDiv) % E) * Bz) + (long)tx * nch * TB;
    }

    auto produce = [&]() {
        if (tid == 0) {
            if (pcount >= NSTG) mbar_wait(emptyB[pslot], pph ^ 1);
            mbar_expect_tx(fullB[pslot], STB);
            bulk_g2s(smBase + pslot * STB,         pgA + (long)pStage * (KG * TB), KG * TB, fullB[pslot]);
            bulk_g2s(smBase + pslot * STB + KG*TB, pgB + (long)pStage * (KG * TB), KG * TB, fullB[pslot]);
        }
        ++pcount;
        if (++pslot == NSTG) { pslot = 0; pph ^= 1; }
        if (++pStage == spt) {
            pStage = 0; ptile += G;
            if (ptile < nTiles) {
                int z = ptile / tXY, r0 = ptile - z * tXY, ty = r0 / tX, tx = r0 - ty * tX;
                pgA = (const char*)(Ap + (long)z * Az) + (long)ty * nch * TB;
                pgB = (const char*)(Bp + (long)((z / bDiv) % E) * Bz) + (long)tx * nch * TB;
            }
        }
    };

    for (int i = 0; i < NSTG - 1 && i < myStages; ++i) produce();

    float acc[2][8][4];
    #pragma unroll
    for (int a = 0; a < 2; ++a)
        #pragma unroll
        for (int b = 0; b < 8; ++b)
            #pragma unroll
            for (int q = 0; q < 4; ++q) acc[a][b][q] = 0.0f;

    int cs = 0, cp = 0, cKg = 0, ctile = bid;

    for (int s = 0; s < myStages; ++s) {
        if (s + NSTG - 1 < myStages) produce();
        mbar_wait(fullB[cs], cp);

        const unsigned stg = smBase + cs * STB;
        #pragma unroll
        for (int kg = 0; kg < KG; ++kg) {
            const unsigned aB = stg + kg * TB;
            const unsigned bB = stg + KG * TB + kg * TB;
            #pragma unroll
            for (int ks = 0; ks < 2; ++ks) {
                unsigned aH[2][4];
                #pragma unroll
                for (int mt = 0; mt < 2; ++mt) {
                    unsigned r = wm * 32 + mt * 16 + (lane & 15);
                    unsigned cu = (unsigned)(ks * 2 + (lane >> 4));
                    LDSM_X4(aH[mt], aB + r * 64 + ((cu ^ ((r >> 1) & 3)) << 4));
                }
                #pragma unroll
                for (int p = 0; p < 4; ++p) {
                    unsigned bH[4];
                    unsigned r = wn * 64 + p * 16 + (lane & 7) + ((lane >> 4) << 3);
                    unsigned cu = (unsigned)(ks * 2 + ((lane >> 3) & 1));
                    LDSM_X4(bH, bB + r * 64 + ((cu ^ ((r >> 1) & 3)) << 4));
                    #pragma unroll
                    for (int mt = 0; mt < 2; ++mt)
                        #pragma unroll
                        for (int s2 = 0; s2 < 2; ++s2)
                            MMA_F16(acc[mt][p * 2 + s2], aH[mt], bH + 2 * s2);
                }
            }
        }
        if (lane == 0) mbar_arrive(emptyB[cs]);
        if (++cs == NSTG) { cs = 0; cp ^= 1; }

        if (++cKg == spt) {
            // ---- epilogue for ctile ----
            int z = ctile / tXY, r0 = ctile - z * tXY, ty = r0 / tX, tx = r0 - ty * tX;
            const int crow = ty * 128, ccol = tx * 128;
            const int bIdx = (z / bDiv) % E;
            const float* bias = (EPI == 1 || EPI == 3) ? (biasBase + (long)bIdx * biasZ) : nullptr;

            #pragma unroll
            for (int mt = 0; mt < 2; ++mt) {
                #pragma unroll
                for (int half = 0; half < 2; ++half) {
                    const int r = crow + wm * 32 + mt * 16 + gid + 8 * half;
                    if (EPI <= 1) {
                        unsigned short* dstz = (unsigned short*)Cout + (long)z * Cz;
                        long rowBase = (long)(r >> 7) * (Nn >> 5) * 4096 + (long)(r & 127) * 32;
                        const unsigned rsw = (unsigned)((r >> 1) & 3);
                        #pragma unroll
                        for (int nj = 0; nj < 8; ++nj) {
                            const int cg = ccol + wn * 64 + nj * 8 + 2 * tig;
                            float v0 = acc[mt][nj][2 * half];
                            float v1 = acc[mt][nj][2 * half + 1];
                            if (EPI == 1) {
                                v0 = gelu(v0 + bias[cg]);
                                v1 = gelu(v1 + bias[cg + 1]);
                            }
                            const int g = cg >> 5, j = cg & 31;
                            long tb = rowBase + (long)g * 4096;
                            unsigned u = (unsigned)(j >> 3);
                            int jp = (int)(((u ^ rsw) << 3) | (unsigned)(j & 7));
                            *(unsigned*)(dstz + tb + jp) = pack2h(v0, v1);
                        }
                    } else {
                        float* dst = (float*)Cout + (long)z * Cz + (long)r * ldc;
                        #pragma unroll
                        for (int nj = 0; nj < 8; ++nj) {
                            const int cg = ccol + wn * 64 + nj * 8 + 2 * tig;
                            float v0 = acc[mt][nj][2 * half];
                            float v1 = acc[mt][nj][2 * half + 1];
                            if (EPI == 3) { v0 += bias[cg]; v1 += bias[cg + 1]; }
                            float2 p; p.x = v0; p.y = v1;
                            *(float2*)(dst + cg) = p;
                        }
                    }
                }
            }
            cKg = 0; ctile += G;
            #pragma unroll
            for (int a = 0; a < 2; ++a)
                #pragma unroll
                for (int b = 0; b < 8; ++b)
                    #pragma unroll
                    for (int q = 0; q < 4; ++q) acc[a][b][q] = 0.0f;
        }
    }
}

} // namespace

extern "C" void kernel_launch(void* const* d_in, const int* in_sizes, int n_in,
                              void* d_out, int out_size)
{
    const float* x    = (const float*)d_in[0];
    const float* dm   = (const float*)d_in[1];
    const float* comb = (const float*)d_in[2];
    const float* w1   = (const float*)d_in[3];
    const float* b1   = (const float*)d_in[4];
    const float* w2   = (const float*)d_in[5];
    const float* b2   = (const float*)d_in[6];
    float* out = (float*)d_out;

    unsigned short *A1p, *B1p, *B2p, *B3p, *A2p, *A3p, *B4p, *A4p;
    float* yscr;
    cudaGetSymbolAddress((void**)&A1p, g_A1p);
    cudaGetSymbolAddress((void**)&B1p, g_B1p);
    cudaGetSymbolAddress((void**)&B2p, g_B2p);
    cudaGetSymbolAddress((void**)&B3p, g_B3p);
    cudaGetSymbolAddress((void**)&A2p, g_A2p);
    cudaGetSymbolAddress((void**)&A3p, g_A3p);
    cudaGetSymbolAddress((void**)&B4p, g_B4p);
    cudaGetSymbolAddress((void**)&A4p, g_A4p);
    cudaGetSymbolAddress((void**)&yscr, g_y);

    cudaFuncSetAttribute(bgemm<0,2,3>, cudaFuncAttributeMaxDynamicSharedMemorySize, SMEM_DYN);
    cudaFuncSetAttribute(bgemm<1,2,3>, cudaFuncAttributeMaxDynamicSharedMemorySize, SMEM_DYN);
    cudaFuncSetAttribute(bgemm<2,2,3>, cudaFuncAttributeMaxDynamicSharedMemorySize, SMEM_DYN);
    cudaFuncSetAttribute(bgemm<3,2,3>, cudaFuncAttributeMaxDynamicSharedMemorySize, SMEM_DYN);

    // #1 dm^T -> A1p: per (b,e)
    pack_hi_t<<<dim3(C/128, T/32, Bsz*E), 256>>>(dm, A1p, T, E*C,
        (long)T*E*C, (long)C, E, (long)C*T);
    // #2 x^T -> B1p: per b
    pack_hi_t<<<dim3(D/128, T/32, Bsz), 256>>>(x, B1p, T, D,
        (long)T*D, 0L, 1, (long)D*T);
    // #3 w1^T -> B2p: per e
    pack_hi_t<<<dim3(HE/128, D/32, E), 256>>>(w1, B2p, D, HE,
        (long)D*HE, 0L, 1, (long)HE*D);
    // #4 S1: xd = dm^T * x  (M=C, N=D, K=T) -> A2p (hi)   [profiled slot]
    {
        int nT = (D/128) * (C/128) * (Bsz*E);   // 512
        bgemm<0,2,3><<<(nT < GMAX ? nT : GMAX), 256, SMEM_DYN>>>(
            A1p, B1p, A2p, nullptr, T, D, D,
            (long)C*T, (long)D*T, (long)C*D, 0L,
            4, D/128, (D/128)*(C/128), nT);
    }
    // #5 w2^T -> B3p: per e
    pack_hi_t<<<dim3(O/128, HE/32, E), 256>>>(w2, B3p, HE, O,
        (long)HE*O, 0L, 1, (long)O*HE);
    // #6 comb -> A4p
    {
        long nUnits = (long)Bsz * T * E * C / 8;
        pack_hi_nt<<<(unsigned)((nUnits + 255) / 256), 256>>>(comb, A4p, nUnits, E*C);
    }
    // #7 S2: h = gelu(xd*w1 + b1)  (K=D) -> A3p (hi)
    {
        int nT = (HE/128) * (C/128) * (Bsz*E);  // 512
        bgemm<1,2,3><<<(nT < GMAX ? nT : GMAX), 256, SMEM_DYN>>>(
            A2p, B2p, A3p, b1, D, HE, HE,
            (long)C*D, (long)HE*D, (long)C*HE, (long)HE,
            1, HE/128, (HE/128)*(C/128), nT);
    }
    // #8 S3: y = h*w2  (K=HE) fp32 -> yscr
    {
        int nT = (O/128) * (C/128) * (Bsz*E);   // 512
        bgemm<2,2,3><<<(nT < GMAX ? nT : GMAX), 256, SMEM_DYN>>>(
            A3p, B3p, yscr, nullptr, HE, O, O,
            (long)C*HE, (long)O*HE, (long)C*O, 0L,
            1, O/128, (O/128)*(C/128), nT);
    }
    // #9 y^T -> B4p: per b
    pack_hi_t<<<dim3(O/128, (E*C)/32, Bsz), 256>>>(yscr, B4p, E*C, O,
        (long)E*C*O, 0L, 1, (long)O*E*C);
    // #10 S4: out = comb * y^T + b2  (M=T, N=O, K=EC) fp32 out
    {
        int nT = (O/128) * (T/128) * Bsz;       // 256
        bgemm<3,2,3><<<(nT < GMAX ? nT : GMAX), 256, SMEM_DYN>>>(
            A4p, B4p, out, b2, E*C, O, O,
            (long)T*E*C, (long)O*E*C, (long)T*O, 0L,
            1, O/128, (O/128)*(T/128), nT);
    }
}

// round 13
// speedup vs baseline: 1.1527x; 1.0120x over previous
#include <cuda_runtime.h>
#include <cuda_fp16.h>
#include <math.h>

namespace {

constexpr int Bsz = 4, T = 2048, D = 512, E = 4, C = 1024, HE = 512, O = 512;
constexpr int GMAX = 296;   // 148 SMs x 2 CTAs
constexpr int SMEM_RING3 = 3 * 32768 + 1024;            // KG=2, NSTG=3
constexpr int SMEM_S3    = 4 * 16384 + 34816 + 1024;    // KG=1, NSTG=4 + 128x136 stage

// ALL operands hi-only fp16, blob per (128-row tile, 32-k chunk):
//   [row 0..127][32 halfs; 16B-unit u in 0..3 at u^((row>>1)&3)]  (4096 halfs = 8KB)
__device__ __align__(256) unsigned short g_A1p[(size_t)Bsz*E*C*T];      // dm^T [be]
__device__ __align__(256) unsigned short g_B1p[(size_t)Bsz*D*T];        // x^T  [b]
__device__ __align__(256) unsigned short g_B2p[(size_t)E*HE*D];         // w1^T [e]
__device__ __align__(256) unsigned short g_B3p[(size_t)E*O*HE];         // w2^T [e]
__device__ __align__(256) unsigned short g_A2p[(size_t)Bsz*E*C*D];      // xd   [be]
__device__ __align__(256) unsigned short g_A3p[(size_t)Bsz*E*C*HE];     // h    [be]
__device__ __align__(256) unsigned short g_B4p[(size_t)Bsz*O*E*C];      // y^T  [b]
__device__ __align__(256) unsigned short g_A4p[(size_t)Bsz*T*E*C];      // comb [b]

__device__ __forceinline__ unsigned smem_u32(const void* p) {
    unsigned a;
    asm("{ .reg .u64 t; cvta.to.shared.u64 t, %1; cvt.u32.u64 %0, t; }" : "=r"(a) : "l"(p));
    return a;
}
__device__ __forceinline__ float gelu(float v) {
    return 0.5f * v * (1.0f + erff(v * 0.70710678118654752f));
}
__device__ __forceinline__ unsigned pack2h(float a, float b) {
    __half2 p; p.x = __float2half_rn(a); p.y = __float2half_rn(b);
    return *(unsigned*)&p;
}

__device__ __forceinline__ void mbar_init(unsigned a, unsigned cnt) {
    asm volatile("mbarrier.init.shared.b64 [%0], %1;" :: "r"(a), "r"(cnt) : "memory");
}
__device__ __forceinline__ void mbar_arrive(unsigned a) {
    asm volatile("mbarrier.arrive.shared.b64 _, [%0];" :: "r"(a) : "memory");
}
__device__ __forceinline__ void mbar_expect_tx(unsigned a, unsigned bytes) {
    asm volatile("mbarrier.arrive.expect_tx.shared.b64 _, [%0], %1;"
                 :: "r"(a), "r"(bytes) : "memory");
}
__device__ __forceinline__ void mbar_wait(unsigned a, unsigned par) {
    asm volatile("{\n\t.reg .pred P;\n"
                 "WL%=:\n\t"
                 "mbarrier.try_wait.parity.acquire.cta.shared::cta.b64 P, [%0], %1, 0x989680;\n\t"
                 "@P bra.uni WD%=;\n\t"
                 "bra.uni WL%=;\n"
                 "WD%=:\n\t}" :: "r"(a), "r"(par) : "memory");
}
__device__ __forceinline__ void bulk_g2s(unsigned dst, const void* src,
                                         unsigned bytes, unsigned mbar) {
    asm volatile("cp.async.bulk.shared::cluster.global.mbarrier::complete_tx::bytes "
                 "[%0], [%1], %2, [%3];"
                 :: "r"(dst), "l"(src), "r"(bytes), "r"(mbar) : "memory");
}

#define LDSM_X4(R, addr) \
    asm volatile("ldmatrix.sync.aligned.m8n8.x4.shared.b16 {%0,%1,%2,%3}, [%4];" \
        : "=r"((R)[0]), "=r"((R)[1]), "=r"((R)[2]), "=r"((R)[3]) : "r"(addr))

#define MMA_F16(Cc, Aa, Bb) \
    asm volatile("mma.sync.aligned.m16n8k16.row.col.f32.f16.f16.f32 " \
        "{%0,%1,%2,%3}, {%4,%5,%6,%7}, {%8,%9}, {%0,%1,%2,%3};" \
        : "+f"((Cc)[0]), "+f"((Cc)[1]), "+f"((Cc)[2]), "+f"((Cc)[3]) \
        : "r"((Aa)[0]), "r"((Aa)[1]), "r"((Aa)[2]), "r"((Aa)[3]), \
          "r"((Bb)[0]), "r"((Bb)[1]))

// ---------------- coalesced hi-only pack kernels ----------------
__global__ void pack_hi_t(const float* __restrict__ inBase, unsigned short* __restrict__ outRaw,
                          int Kdim, int rs, long inZdiv, long inZmod, int zdiv, long outZ) {
    int z = blockIdx.z;
    const float* in = inBase + (long)(z / zdiv) * inZdiv + (long)(z % zdiv) * inZmod;
    __half* out = (__half*)outRaw + (long)z * outZ;
    __shared__ float t[32][132];
    const int m0 = blockIdx.x * 128, k0 = blockIdx.y * 32;
    const int tid = threadIdx.x;
    const int lr = tid >> 5, lc = (tid & 31) * 4;
    #pragma unroll
    for (int i = 0; i < 4; ++i) {
        float4 v = *(const float4*)&in[(long)(k0 + lr + 8*i) * rs + m0 + lc];
        t[lr + 8*i][lc] = v.x; t[lr + 8*i][lc+1] = v.y;
        t[lr + 8*i][lc+2] = v.z; t[lr + 8*i][lc+3] = v.w;
    }
    __syncthreads();
    const int m = tid >> 1, hf = tid & 1;
    const int mg = m0 + m;
    long blob = ((long)(mg >> 7) * (Kdim >> 5) + blockIdx.y) * 4096 + (mg & 127) * 32;
    const unsigned sw = (unsigned)((mg >> 1) & 3);
    unsigned w[4], w2[4];
    #pragma unroll
    for (int q = 0; q < 4; ++q)
        w[q] = pack2h(t[hf*16 + q*2][m], t[hf*16 + q*2 + 1][m]);
    #pragma unroll
    for (int q = 0; q < 4; ++q)
        w2[q] = pack2h(t[hf*16 + 8 + q*2][m], t[hf*16 + 8 + q*2 + 1][m]);
    const unsigned u0 = (unsigned)(hf * 2), u1 = u0 + 1;
    *(uint4*)(out + blob + ((u0 ^ sw) << 3)) = make_uint4(w[0], w[1], w[2], w[3]);
    *(uint4*)(out + blob + ((u1 ^ sw) << 3)) = make_uint4(w2[0], w2[1], w2[2], w2[3]);
}

__global__ void pack_hi_nt(const float* __restrict__ in, unsigned short* __restrict__ outRaw,
                           long nUnits, int Kdim) {
    long i = (long)blockIdx.x * blockDim.x + threadIdx.x;
    if (i >= nUnits) return;
    const int upr = Kdim >> 3;
    long r = i / upr; int uq = (int)(i % upr);
    int g = uq >> 2, u = uq & 3;
    const float* src = in + r * Kdim + g * 32 + u * 8;
    float4 a = *(const float4*)src, b = *(const float4*)(src + 4);
    __half* out = (__half*)outRaw;
    long blob = ((r >> 7) * (long)(Kdim >> 5) + g) * 4096 + (r & 127) * 32;
    unsigned sw = (unsigned)((r >> 1) & 3);
    *(uint4*)(out + blob + ((((unsigned)u) ^ sw) << 3)) =
        make_uint4(pack2h(a.x, a.y), pack2h(a.z, a.w), pack2h(b.x, b.y), pack2h(b.z, b.w));
}

// ------- persistent mma.sync fp16 GEMM (all-hi), TMA-bulk, continuous producer -------
// C = A_hi * B_hi
// EPI: 0 = packed hi out; 1 = + bias + GELU; 2 = fp32 out; 3 = fp32 out + bias;
//      4 = TRANSPOSED packed hi out (y^T for S3; hardcodes b = z/E, kbase = (z%E)*C + crow)
template <int EPI, int KG, int NSTG>
__global__ __launch_bounds__(256, 2)
void bgemm(const unsigned short* __restrict__ Ap,
           const unsigned short* __restrict__ Bp,
           void* __restrict__ Cout,
           const float* __restrict__ biasBase,
           int K, int Nn, int ldc,
           long Az, long Bz, long Cz, long biasZ,
           int bDiv, int tX, int tXY, int nTiles)
{
    constexpr int TB = 8192;
    constexpr int STB = KG * 2 * TB;
    extern __shared__ char dynsm[];
    __shared__ __align__(8) unsigned long long s_full[NSTG], s_empty[NSTG];

    const int bid = blockIdx.x, G = gridDim.x;
    if (bid >= nTiles) return;
    char* dynA = dynsm + (((smem_u32(dynsm) + 1023u) & ~1023u) - smem_u32(dynsm));
    const unsigned smBase = smem_u32(dynA);
    __half* stage = (EPI == 4) ? (__half*)(dynA + NSTG * STB) : nullptr;

    const int tid  = threadIdx.x;
    const int lane = tid & 31;
    const int warp = tid >> 5;
    const int wm   = warp & 3;
    const int wn   = warp >> 2;
    const int gid  = lane >> 2, tig = lane & 3;

    const int nch = K / 32, spt = nch / KG;
    const int myTiles  = (nTiles - bid + G - 1) / G;
    const int myStages = myTiles * spt;

    unsigned fullB[NSTG], emptyB[NSTG];
    #pragma unroll
    for (int s = 0; s < NSTG; ++s) {
        fullB[s]  = smem_u32(&s_full[s]);
        emptyB[s] = smem_u32(&s_empty[s]);
    }
    if (tid == 0) {
        #pragma unroll
        for (int s = 0; s < NSTG; ++s) { mbar_init(fullB[s], 1); mbar_init(emptyB[s], 8); }
    }
    __syncthreads();

    // ---- producer state (continuous across tiles) ----
    int ptile = bid, pStage = 0, pslot = 0, pph = 0, pcount = 0;
    const char *pgA, *pgB;
    {
        int z = ptile / tXY, r0 = ptile - z * tXY, ty = r0 / tX, tx = r0 - ty * tX;
        pgA = (const char*)(Ap + (long)z * Az) + (long)ty * nch * TB;
        pgB = (const char*)(Bp + (long)((z / bDiv) % E) * Bz) + (long)tx * nch * TB;
    }

    auto produce = [&]() {
        if (tid == 0) {
            if (pcount >= NSTG) mbar_wait(emptyB[pslot], pph ^ 1);
            mbar_expect_tx(fullB[pslot], STB);
            bulk_g2s(smBase + pslot * STB,         pgA + (long)pStage * (KG * TB), KG * TB, fullB[pslot]);
            bulk_g2s(smBase + pslot * STB + KG*TB, pgB + (long)pStage * (KG * TB), KG * TB, fullB[pslot]);
        }
        ++pcount;
        if (++pslot == NSTG) { pslot = 0; pph ^= 1; }
        if (++pStage == spt) {
            pStage = 0; ptile += G;
            if (ptile < nTiles) {
                int z = ptile / tXY, r0 = ptile - z * tXY, ty = r0 / tX, tx = r0 - ty * tX;
                pgA = (const char*)(Ap + (long)z * Az) + (long)ty * nch * TB;
                pgB = (const char*)(Bp + (long)((z / bDiv) % E) * Bz) + (long)tx * nch * TB;
            }
        }
    };

    for (int i = 0; i < NSTG - 1 && i < myStages; ++i) produce();

    float acc[2][8][4];
    #pragma unroll
    for (int a = 0; a < 2; ++a)
        #pragma unroll
        for (int b = 0; b < 8; ++b)
            #pragma unroll
            for (int q = 0; q < 4; ++q) acc[a][b][q] = 0.0f;

    int cs = 0, cp = 0, cKg = 0, ctile = bid;

    for (int s = 0; s < myStages; ++s) {
        if (s + NSTG - 1 < myStages) produce();
        mbar_wait(fullB[cs], cp);

        const unsigned stg = smBase + cs * STB;
        #pragma unroll
        for (int kg = 0; kg < KG; ++kg) {
            const unsigned aB = stg + kg * TB;
            const unsigned bB = stg + KG * TB + kg * TB;
            #pragma unroll
            for (int ks = 0; ks < 2; ++ks) {
                unsigned aH[2][4];
                #pragma unroll
                for (int mt = 0; mt < 2; ++mt) {
                    unsigned r = wm * 32 + mt * 16 + (lane & 15);
                    unsigned cu = (unsigned)(ks * 2 + (lane >> 4));
                    LDSM_X4(aH[mt], aB + r * 64 + ((cu ^ ((r >> 1) & 3)) << 4));
                }
                #pragma unroll
                for (int p = 0; p < 4; ++p) {
                    unsigned bH[4];
                    unsigned r = wn * 64 + p * 16 + (lane & 7) + ((lane >> 4) << 3);
                    unsigned cu = (unsigned)(ks * 2 + ((lane >> 3) & 1));
                    LDSM_X4(bH, bB + r * 64 + ((cu ^ ((r >> 1) & 3)) << 4));
                    #pragma unroll
                    for (int mt = 0; mt < 2; ++mt)
                        #pragma unroll
                        for (int s2 = 0; s2 < 2; ++s2)
                            MMA_F16(acc[mt][p * 2 + s2], aH[mt], bH + 2 * s2);
                }
            }
        }
        if (lane == 0) mbar_arrive(emptyB[cs]);
        if (++cs == NSTG) { cs = 0; cp ^= 1; }

        if (++cKg == spt) {
            // ---- epilogue for ctile ----
            int z = ctile / tXY, r0 = ctile - z * tXY, ty = r0 / tX, tx = r0 - ty * tX;
            const int crow = ty * 128, ccol = tx * 128;
            const int bIdx = (z / bDiv) % E;
            const float* bias = (EPI == 1 || EPI == 3) ? (biasBase + (long)bIdx * biasZ) : nullptr;

            if (EPI == 4) {
                // stage transposed fp16 tile: stage[o_local][c_local], stride 136 halves
                #pragma unroll
                for (int mt = 0; mt < 2; ++mt)
                    #pragma unroll
                    for (int half = 0; half < 2; ++half) {
                        const int cl = wm * 32 + mt * 16 + gid + 8 * half;
                        #pragma unroll
                        for (int nj = 0; nj < 8; ++nj) {
                            const int og = wn * 64 + nj * 8 + 2 * tig;
                            stage[og * 136 + cl]       = __float2half_rn(acc[mt][nj][2 * half]);
                            stage[(og + 1) * 136 + cl] = __float2half_rn(acc[mt][nj][2 * half + 1]);
                        }
                    }
                __syncthreads();
                {
                    const int b = z >> 2;                       // E = 4
                    const long kbase = (long)(z & 3) * C + crow;
                    unsigned short* dstz = (unsigned short*)Cout + (long)b * Cz;
                    const long rowBlk = (long)((ccol) >> 7) * 128;   // (EC>>5) = 128
                    #pragma unroll
                    for (int it = 0; it < 2; ++it) {
                        int item = tid + it * 256;
                        int ol = item & 127, gi = item >> 7;
                        long gG = (kbase >> 5) + gi;
                        long blob = (rowBlk + gG) * 4096 + ol * 32;
                        const uint4* src = (const uint4*)(stage + ol * 136 + gi * 32);
                        unsigned rsw = (unsigned)(((unsigned)ol >> 1) & 3);
                        uint4* d = (uint4*)(dstz + blob);
                        d[0 ^ rsw] = src[0];
                        d[1 ^ rsw] = src[1];
                        d[2 ^ rsw] = src[2];
                        d[3 ^ rsw] = src[3];
                    }
                }
                __syncthreads();
            } else {
                #pragma unroll
                for (int mt = 0; mt < 2; ++mt) {
                    #pragma unroll
                    for (int half = 0; half < 2; ++half) {
                        const int r = crow + wm * 32 + mt * 16 + gid + 8 * half;
                        if (EPI <= 1) {
                            unsigned short* dstz = (unsigned short*)Cout + (long)z * Cz;
                            long rowBase = (long)(r >> 7) * (Nn >> 5) * 4096 + (long)(r & 127) * 32;
                            const unsigned rsw = (unsigned)((r >> 1) & 3);
                            #pragma unroll
                            for (int nj = 0; nj < 8; ++nj) {
                                const int cg = ccol + wn * 64 + nj * 8 + 2 * tig;
                                float v0 = acc[mt][nj][2 * half];
                                float v1 = acc[mt][nj][2 * half + 1];
                                if (EPI == 1) {
                                    v0 = gelu(v0 + bias[cg]);
                                    v1 = gelu(v1 + bias[cg + 1]);
                                }
                                const int g = cg >> 5, j = cg & 31;
                                long tb = rowBase + (long)g * 4096;
                                unsigned u = (unsigned)(j >> 3);
                                int jp = (int)(((u ^ rsw) << 3) | (unsigned)(j & 7));
                                *(unsigned*)(dstz + tb + jp) = pack2h(v0, v1);
                            }
                        } else {
                            float* dst = (float*)Cout + (long)z * Cz + (long)r * ldc;
                            #pragma unroll
                            for (int nj = 0; nj < 8; ++nj) {
                                const int cg = ccol + wn * 64 + nj * 8 + 2 * tig;
                                float v0 = acc[mt][nj][2 * half];
                                float v1 = acc[mt][nj][2 * half + 1];
                                if (EPI == 3) { v0 += bias[cg]; v1 += bias[cg + 1]; }
                                float2 p; p.x = v0; p.y = v1;
                                *(float2*)(dst + cg) = p;
                            }
                        }
                    }
                }
            }
            cKg = 0; ctile += G;
            #pragma unroll
            for (int a = 0; a < 2; ++a)
                #pragma unroll
                for (int b = 0; b < 8; ++b)
                    #pragma unroll
                    for (int q = 0; q < 4; ++q) acc[a][b][q] = 0.0f;
        }
    }
}

} // namespace

extern "C" void kernel_launch(void* const* d_in, const int* in_sizes, int n_in,
                              void* d_out, int out_size)
{
    const float* x    = (const float*)d_in[0];
    const float* dm   = (const float*)d_in[1];
    const float* comb = (const float*)d_in[2];
    const float* w1   = (const float*)d_in[3];
    const float* b1   = (const float*)d_in[4];
    const float* w2   = (const float*)d_in[5];
    const float* b2   = (const float*)d_in[6];
    float* out = (float*)d_out;

    unsigned short *A1p, *B1p, *B2p, *B3p, *A2p, *A3p, *B4p, *A4p;
    cudaGetSymbolAddress((void**)&A1p, g_A1p);
    cudaGetSymbolAddress((void**)&B1p, g_B1p);
    cudaGetSymbolAddress((void**)&B2p, g_B2p);
    cudaGetSymbolAddress((void**)&B3p, g_B3p);
    cudaGetSymbolAddress((void**)&A2p, g_A2p);
    cudaGetSymbolAddress((void**)&A3p, g_A3p);
    cudaGetSymbolAddress((void**)&B4p, g_B4p);
    cudaGetSymbolAddress((void**)&A4p, g_A4p);

    cudaFuncSetAttribute(bgemm<0,2,3>, cudaFuncAttributeMaxDynamicSharedMemorySize, SMEM_RING3);
    cudaFuncSetAttribute(bgemm<1,2,3>, cudaFuncAttributeMaxDynamicSharedMemorySize, SMEM_RING3);
    cudaFuncSetAttribute(bgemm<4,1,4>, cudaFuncAttributeMaxDynamicSharedMemorySize, SMEM_S3);
    cudaFuncSetAttribute(bgemm<3,2,3>, cudaFuncAttributeMaxDynamicSharedMemorySize, SMEM_RING3);

    // #1 dm^T -> A1p: per (b,e)
    pack_hi_t<<<dim3(C/128, T/32, Bsz*E), 256>>>(dm, A1p, T, E*C,
        (long)T*E*C, (long)C, E, (long)C*T);
    // #2 x^T -> B1p: per b
    pack_hi_t<<<dim3(D/128, T/32, Bsz), 256>>>(x, B1p, T, D,
        (long)T*D, 0L, 1, (long)D*T);
    // #3 w1^T -> B2p: per e
    pack_hi_t<<<dim3(HE/128, D/32, E), 256>>>(w1, B2p, D, HE,
        (long)D*HE, 0L, 1, (long)HE*D);
    // #4 S1: xd = dm^T * x  (M=C, N=D, K=T) -> A2p (hi)   [profiled slot]
    {
        int nT = (D/128) * (C/128) * (Bsz*E);   // 512
        bgemm<0,2,3><<<(nT < GMAX ? nT : GMAX), 256, SMEM_RING3>>>(
            A1p, B1p, A2p, nullptr, T, D, D,
            (long)C*T, (long)D*T, (long)C*D, 0L,
            4, D/128, (D/128)*(C/128), nT);
    }
    // #5 w2^T -> B3p: per e
    pack_hi_t<<<dim3(O/128, HE/32, E), 256>>>(w2, B3p, HE, O,
        (long)HE*O, 0L, 1, (long)O*HE);
    // #6 comb -> A4p
    {
        long nUnits = (long)Bsz * T * E * C / 8;
        pack_hi_nt<<<(unsigned)((nUnits + 255) / 256), 256>>>(comb, A4p, nUnits, E*C);
    }
    // #7 S2: h = gelu(xd*w1 + b1)  (K=D) -> A3p (hi)
    {
        int nT = (HE/128) * (C/128) * (Bsz*E);  // 512
        bgemm<1,2,3><<<(nT < GMAX ? nT : GMAX), 256, SMEM_RING3>>>(
            A2p, B2p, A3p, b1, D, HE, HE,
            (long)C*D, (long)HE*D, (long)C*HE, (long)HE,
            1, HE/128, (HE/128)*(C/128), nT);
    }
    // #8 S3: y^T fused pack (K=HE) -> B4p directly (EPI=4)
    {
        int nT = (O/128) * (C/128) * (Bsz*E);   // 512
        bgemm<4,1,4><<<(nT < GMAX ? nT : GMAX), 256, SMEM_S3>>>(
            A3p, B3p, B4p, nullptr, HE, O, O,
            (long)C*HE, (long)O*HE, (long)O*E*C, 0L,
            1, O/128, (O/128)*(C/128), nT);
    }
    // #9 S4: out = comb * y^T + b2  (M=T, N=O, K=EC) fp32 out
    {
        int nT = (O/128) * (T/128) * Bsz;       // 256
        bgemm<3,2,3><<<(nT < GMAX ? nT : GMAX), 256, SMEM_RING3>>>(
            A4p, B4p, out, b2, E*C, O, O,
            (long)T*E*C, (long)O*E*C, (long)T*O, 0L,
            1, O/128, (O/128)*(T/128), nT);
    }
}